// round 2
// baseline (speedup 1.0000x reference)
#include <cuda_runtime.h>
#include <cstdint>
#include <cstddef>

typedef unsigned long long u64;

// ---- packed f32x2 helpers (Blackwell sm_103a) ----
#define FMA2(d, a, b, c) asm("fma.rn.f32x2 %0, %1, %2, %3;" : "=l"(d) : "l"(a), "l"(b), "l"(c))
#define MUL2(d, a, b)    asm("mul.rn.f32x2 %0, %1, %2;"     : "=l"(d) : "l"(a), "l"(b))

__device__ __forceinline__ u64 pack2(float lo, float hi) {
    u64 r; asm("mov.b64 %0, {%1, %2};" : "=l"(r) : "f"(lo), "f"(hi)); return r;
}
__device__ __forceinline__ float2 unpack2(u64 v) {
    float2 r; asm("mov.b64 {%0, %1}, %2;" : "=f"(r.x), "=f"(r.y) : "l"(v)); return r;
}
__device__ __forceinline__ u64 dup2(float v) {
    u64 r; asm("mov.b64 %0, {%1, %1};" : "=l"(r) : "f"(v)); return r;
}

constexpr int E_DIM    = 1024;
constexpr int MAX_ROWS = 32768;       // B*S for this problem
constexpr int RPB      = 64;          // rows per block (both kernels)

// q scratch between the two kernels (1 MB)
__device__ float g_q[MAX_ROWS * 8];

// ============================================================================
// Kernel 1: h = x @ w1^T + b1 ; q = Pauli-Z cosine-string products
// Circuit (RX layer + 2x(CNOT ladder + H_7)) reduces analytically to:
//   q0=c0, q1=c1, q2=c0c2, q3=c1c3, q4=c0c2c4, q5=c1c3c5, q6=c0c2c4c6,
//   q7=c0c1c2c3c4c5c6c7   with c_i = cos(h_i)
// 8 warps per row-group; warp owns a 128-wide e-slice with w1 in registers.
// ============================================================================
__global__ void __launch_bounds__(256, 3)
ffq_phase1(const float* __restrict__ x, const float* __restrict__ w1,
           const float* __restrict__ b1, int rows)
{
    __shared__ float s_part[8][8][8];      // [row][f][warp]

    const int tid  = threadIdx.x;
    const int warp = tid >> 5;
    const int lane = tid & 31;

    const int e1 = warp * 128 + lane * 4;
    u64 wa[8], wb[8];
#pragma unroll
    for (int f = 0; f < 8; f++) {
        float4 v = *reinterpret_cast<const float4*>(w1 + f * E_DIM + e1);
        wa[f] = pack2(v.x, v.y);
        wb[f] = pack2(v.z, v.w);
    }

    const int block_row0 = blockIdx.x * RPB;

    // continuous rolling prefetch: 4 rows in flight per lane at all times
    float4 xr[4];
#pragma unroll
    for (int r = 0; r < 4; r++) {
        int pr = block_row0 + r; if (pr >= rows) pr = rows - 1;
        xr[r] = *reinterpret_cast<const float4*>(x + (size_t)pr * E_DIM + e1);
    }

    for (int g = 0; g < RPB / 8; g++) {
        const int row0 = block_row0 + g * 8;

#pragma unroll
        for (int r = 0; r < 8; r++) {
            float4 xv = xr[r & 3];
            // prefetch row (row0 + r + 4): stays within this group's rows for
            // r<4, streams into the next group's rows for r>=4 (no bubble).
            int pr = row0 + r + 4; if (pr >= rows) pr = rows - 1;
            xr[r & 3] = *reinterpret_cast<const float4*>(
                x + (size_t)pr * E_DIM + e1);

            u64 xA = pack2(xv.x, xv.y);
            u64 xB = pack2(xv.z, xv.w);
            float s[8];
#pragma unroll
            for (int f = 0; f < 8; f++) {
                u64 acc;
                MUL2(acc, xA, wa[f]);
                FMA2(acc, xB, wb[f], acc);
                float2 t = unpack2(acc);
                s[f] = t.x + t.y;
            }
            // value-halving butterfly: 8 partials -> h[f] slice-sum on lanes 4f
            {
                const bool hi = (lane & 16);
#pragma unroll
                for (int k = 0; k < 4; k++) {
                    float send = hi ? s[k]     : s[k + 4];
                    float keep = hi ? s[k + 4] : s[k];
                    s[k] = keep + __shfl_xor_sync(0xffffffffu, send, 16);
                }
            }
            {
                const bool hi = (lane & 8);
#pragma unroll
                for (int k = 0; k < 2; k++) {
                    float send = hi ? s[k]     : s[k + 2];
                    float keep = hi ? s[k + 2] : s[k];
                    s[k] = keep + __shfl_xor_sync(0xffffffffu, send, 8);
                }
            }
            {
                const bool hi = (lane & 4);
                float send = hi ? s[0] : s[1];
                float keep = hi ? s[1] : s[0];
                s[0] = keep + __shfl_xor_sync(0xffffffffu, send, 4);
            }
            s[0] += __shfl_xor_sync(0xffffffffu, s[0], 2);
            s[0] += __shfl_xor_sync(0xffffffffu, s[0], 1);

            if ((lane & 3) == 0)
                s_part[r][lane >> 2][warp] = s[0];
        }
        __syncthreads();

        if (tid < 64) {
            const int r = tid >> 3;
            const int f = tid & 7;
            float h = b1[f];
#pragma unroll
            for (int w = 0; w < 8; w++) h += s_part[r][f][w];
            float c = __cosf(h);

            const int base = lane & 24;        // 8 lanes per row
            float cs[8];
#pragma unroll
            for (int j = 0; j < 8; j++)
                cs[j] = __shfl_sync(0xffffffffu, c, base + j);

            float q;
            if (f == 7) {
                q = cs[0]*cs[1]*cs[2]*cs[3]*cs[4]*cs[5]*cs[6]*cs[7];
            } else {
                q = 1.0f;
#pragma unroll
                for (int j = 0; j < 8; j++)
                    if (j <= f && ((j ^ f) & 1) == 0) q *= cs[j];
            }
            int row = row0 + r;
            if (row < rows) g_q[row * 8 + f] = q;   // 64 contiguous floats
        }
        __syncthreads();
    }
}

// ============================================================================
// Kernel 2: out = q @ w2^T + b2   (pure streaming write, w2 in registers)
// ============================================================================
__global__ void __launch_bounds__(256, 4)
ffq_phase2(const float* __restrict__ w2, const float* __restrict__ b2,
           float* __restrict__ out, int rows)
{
    __shared__ float s_q[RPB * 8];     // 2 KB

    const int tid = threadIdx.x;
    const int e2  = tid * 4;

    // per-thread w2 columns, packed for f32x2
    u64 p01[8], p23[8];
    {
        float we[4][8];
#pragma unroll
        for (int i = 0; i < 4; i++) {
            float4 lo = *reinterpret_cast<const float4*>(w2 + (e2 + i) * 8);
            float4 hi = *reinterpret_cast<const float4*>(w2 + (e2 + i) * 8 + 4);
            we[i][0] = lo.x; we[i][1] = lo.y; we[i][2] = lo.z; we[i][3] = lo.w;
            we[i][4] = hi.x; we[i][5] = hi.y; we[i][6] = hi.z; we[i][7] = hi.w;
        }
#pragma unroll
        for (int f = 0; f < 8; f++) {
            p01[f] = pack2(we[0][f], we[1][f]);
            p23[f] = pack2(we[2][f], we[3][f]);
        }
    }
    u64 b01, b23;
    {
        float4 bv = *reinterpret_cast<const float4*>(b2 + e2);
        b01 = pack2(bv.x, bv.y);
        b23 = pack2(bv.z, bv.w);
    }

    const int row0 = blockIdx.x * RPB;

    // stage this tile's q (RPB*8 floats = 128 float4)
    if (tid < 128) {
        int idx = row0 * 8 + tid * 4;
        float4 v = (idx < rows * 8)
            ? *reinterpret_cast<const float4*>(g_q + idx)
            : make_float4(0.f, 0.f, 0.f, 0.f);
        *reinterpret_cast<float4*>(s_q + tid * 4) = v;
    }
    __syncthreads();

#pragma unroll 4
    for (int r = 0; r < RPB; r++) {
        int row = row0 + r;
        if (row >= rows) break;
        u64 acc01 = b01, acc23 = b23;
#pragma unroll
        for (int f = 0; f < 8; f++) {
            u64 qq = dup2(s_q[r * 8 + f]);     // LDS.32 broadcast + MOV64
            FMA2(acc01, qq, p01[f], acc01);
            FMA2(acc23, qq, p23[f], acc23);
        }
        float2 a = unpack2(acc01);
        float2 b = unpack2(acc23);
        float4 o = make_float4(a.x, a.y, b.x, b.y);
        *reinterpret_cast<float4*>(out + (size_t)row * E_DIM + e2) = o;
    }
}

extern "C" void kernel_launch(void* const* d_in, const int* in_sizes, int n_in,
                              void* d_out, int out_size) {
    const float* x  = (const float*)d_in[0];
    const float* w1 = (const float*)d_in[1];
    const float* b1 = (const float*)d_in[2];
    const float* w2 = (const float*)d_in[3];
    const float* b2 = (const float*)d_in[4];
    float* out = (float*)d_out;

    const int rows   = in_sizes[0] / E_DIM;          // 32768
    const int blocks = (rows + RPB - 1) / RPB;       // 512

    ffq_phase1<<<blocks, 256>>>(x, w1, b1, rows);
    ffq_phase2<<<blocks, 256>>>(w2, b2, out, rows);
}

// round 3
// speedup vs baseline: 1.1455x; 1.1455x over previous
#include <cuda_runtime.h>
#include <cstdint>
#include <cstddef>

typedef unsigned long long u64;

// ---- packed f32x2 helpers (Blackwell sm_103a) ----
#define FMA2(d, a, b, c) asm("fma.rn.f32x2 %0, %1, %2, %3;" : "=l"(d) : "l"(a), "l"(b), "l"(c))
#define MUL2(d, a, b)    asm("mul.rn.f32x2 %0, %1, %2;"     : "=l"(d) : "l"(a), "l"(b))

__device__ __forceinline__ u64 pack2(float lo, float hi) {
    u64 r; asm("mov.b64 %0, {%1, %2};" : "=l"(r) : "f"(lo), "f"(hi)); return r;
}
__device__ __forceinline__ float2 unpack2(u64 v) {
    float2 r; asm("mov.b64 {%0, %1}, %2;" : "=f"(r.x), "=f"(r.y) : "l"(v)); return r;
}
__device__ __forceinline__ uint32_t smem_u32(const void* p) {
    uint32_t a;
    asm("{ .reg .u64 t; cvta.to.shared.u64 t, %1; cvt.u32.u64 %0, t; }" : "=r"(a) : "l"(p));
    return a;
}
__device__ __forceinline__ void mbar_init(uint32_t mbar, uint32_t cnt) {
    asm volatile("mbarrier.init.shared.b64 [%0], %1;" :: "r"(mbar), "r"(cnt) : "memory");
}
__device__ __forceinline__ void mbar_expect_tx(uint32_t mbar, uint32_t bytes) {
    asm volatile("mbarrier.arrive.expect_tx.shared.b64 _, [%0], %1;" :: "r"(mbar), "r"(bytes) : "memory");
}
__device__ __forceinline__ void bulk_g2s(uint32_t dst, const void* src, uint32_t bytes, uint32_t mbar) {
    asm volatile("cp.async.bulk.shared::cta.global.mbarrier::complete_tx::bytes [%0], [%1], %2, [%3];"
                 :: "r"(dst), "l"(src), "r"(bytes), "r"(mbar) : "memory");
}
__device__ __forceinline__ void mbar_wait(uint32_t mbar, uint32_t parity) {
    asm volatile(
        "{\n\t"
        ".reg .pred P1;\n\t"
        "WL_%=:\n\t"
        "mbarrier.try_wait.parity.acquire.cta.shared::cta.b64 P1, [%0], %1, 0x989680;\n\t"
        "@P1 bra.uni WD_%=;\n\t"
        "bra.uni WL_%=;\n\t"
        "WD_%=:\n\t"
        "}"
        :: "r"(mbar), "r"(parity) : "memory");
}

constexpr int E_DIM    = 1024;
constexpr int MAX_ROWS = 32768;

// q scratch between kernels (1 MB)
__device__ float g_q[MAX_ROWS * 8];

// ============================================================================
// Kernel 1: h = x @ w1^T + b1 ; q = Pauli-Z cosine-string products
//   q0=c0, q1=c1, q2=c0c2, q3=c1c3, q4=c0c2c4, q5=c1c3c5, q6=c0c2c4c6,
//   q7=c0..c7  with c_i = cos(h_i)
// x streamed HBM->SMEM with cp.async.bulk double-buffer (4 rows = 16KB/stage);
// compute reads SMEM; w1 register-resident per 128-wide warp e-slice.
// ============================================================================
constexpr int RPB1    = 64;           // rows per block
constexpr int SROWS   = 4;            // rows per pipeline stage
constexpr int NSTAGE  = RPB1 / SROWS; // 16
constexpr int STBYTES = SROWS * E_DIM * 4;  // 16384

__global__ void __launch_bounds__(256, 4)
ffq_phase1(const float* __restrict__ x, const float* __restrict__ w1,
           const float* __restrict__ b1, int rows)
{
    __shared__ __align__(128) float xs[2][SROWS * E_DIM];  // 32 KB ring
    __shared__ float s_part[SROWS][8][8];                  // [row][f][warp]
    __shared__ __align__(8) u64 mbar_s[2];

    const int tid  = threadIdx.x;
    const int warp = tid >> 5;
    const int lane = tid & 31;

    const uint32_t mb0 = smem_u32(&mbar_s[0]);
    const uint32_t mb1 = smem_u32(&mbar_s[1]);
    const uint32_t xs0 = smem_u32(&xs[0][0]);
    const uint32_t xs1 = smem_u32(&xs[1][0]);

    // w1 register-resident: warp owns e-slice [warp*128, warp*128+128)
    const int e1 = warp * 128 + lane * 4;
    u64 wa[8], wb[8];
#pragma unroll
    for (int f = 0; f < 8; f++) {
        ulonglong2 v = *reinterpret_cast<const ulonglong2*>(w1 + f * E_DIM + e1);
        wa[f] = v.x;
        wb[f] = v.y;
    }
    const float bf = b1[tid & 7];

    if (tid == 0) {
        mbar_init(mb0, 1);
        mbar_init(mb1, 1);
    }
    __syncthreads();

    const int   block_row0 = blockIdx.x * RPB1;
    const float* src = x + (size_t)block_row0 * E_DIM;

    // prime both slots
    if (tid == 0) {
        mbar_expect_tx(mb0, STBYTES);
        bulk_g2s(xs0, src, STBYTES, mb0);
        mbar_expect_tx(mb1, STBYTES);
        bulk_g2s(xs1, src + SROWS * E_DIM, STBYTES, mb1);
    }

    for (int s = 0; s < NSTAGE; s++) {
        const int slot = s & 1;
        const int ph   = (s >> 1) & 1;
        mbar_wait(slot ? mb1 : mb0, ph);

#pragma unroll
        for (int r = 0; r < SROWS; r++) {
            ulonglong2 xu = *reinterpret_cast<const ulonglong2*>(
                &xs[slot][r * E_DIM + e1]);

            float sv[8];
#pragma unroll
            for (int f = 0; f < 8; f++) {
                u64 acc;
                MUL2(acc, xu.x, wa[f]);
                FMA2(acc, xu.y, wb[f], acc);
                float2 t = unpack2(acc);
                sv[f] = t.x + t.y;
            }
            // value-halving butterfly: 8 partials -> slice-sum on lanes 4f
            {
                const bool hi = (lane & 16);
#pragma unroll
                for (int k = 0; k < 4; k++) {
                    float send = hi ? sv[k]     : sv[k + 4];
                    float keep = hi ? sv[k + 4] : sv[k];
                    sv[k] = keep + __shfl_xor_sync(0xffffffffu, send, 16);
                }
            }
            {
                const bool hi = (lane & 8);
#pragma unroll
                for (int k = 0; k < 2; k++) {
                    float send = hi ? sv[k]     : sv[k + 2];
                    float keep = hi ? sv[k + 2] : sv[k];
                    sv[k] = keep + __shfl_xor_sync(0xffffffffu, send, 8);
                }
            }
            {
                const bool hi = (lane & 4);
                float send = hi ? sv[0] : sv[1];
                float keep = hi ? sv[1] : sv[0];
                sv[0] = keep + __shfl_xor_sync(0xffffffffu, send, 4);
            }
            sv[0] += __shfl_xor_sync(0xffffffffu, sv[0], 2);
            sv[0] += __shfl_xor_sync(0xffffffffu, sv[0], 1);

            if ((lane & 3) == 0)
                s_part[r][lane >> 2][warp] = sv[0];
        }
        __syncthreads();   // all x reads + s_part writes for this stage done

        // refill this slot for stage s+2 (slot proven drained by the sync)
        if (tid == 0 && s + 2 < NSTAGE) {
            uint32_t dst = slot ? xs1 : xs0;
            mbar_expect_tx(slot ? mb1 : mb0, STBYTES);
            bulk_g2s(dst, src + (size_t)(s + 2) * SROWS * E_DIM, STBYTES,
                     slot ? mb1 : mb0);
        }

        // q computation: 32 threads = 4 rows x 8 f
        if (tid < 32) {
            const int r = tid >> 3;
            const int f = tid & 7;
            float h = bf;
#pragma unroll
            for (int w = 0; w < 8; w++) h += s_part[r][f][w];
            float c = __cosf(h);

            const int base = tid & 24;   // 8 lanes per row
            float cs[8];
#pragma unroll
            for (int j = 0; j < 8; j++)
                cs[j] = __shfl_sync(0xffffffffu, c, base + j);

            float q;
            if (f == 7) {
                q = cs[0]*cs[1]*cs[2]*cs[3]*cs[4]*cs[5]*cs[6]*cs[7];
            } else {
                q = 1.0f;
#pragma unroll
                for (int j = 0; j < 8; j++)
                    if (j <= f && ((j ^ f) & 1) == 0) q *= cs[j];
            }
            g_q[(size_t)(block_row0 + s * SROWS + r) * 8 + f] = q;
        }
        __syncthreads();   // protect s_part before next stage's butterfly
    }
}

// ============================================================================
// Kernel 2: out = q @ w2^T + b2  (streaming write; w2 f-pairs in registers)
// out[row][e] = sum_f q[row][f] * w2[e][f] + b2[e]
// Packed form: acc2[e] = sum_j (q2j,q2j+1) .* (w2[e][2j], w2[e][2j+1]);
//              out = hadd(acc2) + b2.
// ============================================================================
constexpr int RPB2 = 32;

__global__ void __launch_bounds__(256, 4)
ffq_phase2(const float* __restrict__ w2, const float* __restrict__ b2,
           float* __restrict__ out, int rows)
{
    __shared__ float s_q[RPB2 * 8];    // 1 KB

    const int tid = threadIdx.x;
    const int e2  = tid * 4;

    // per-thread w2 for 4 output columns; f-pairs are contiguous in w2[e][8]
    u64 wp[4][4];
#pragma unroll
    for (int i = 0; i < 4; i++) {
        ulonglong2 v0 = *reinterpret_cast<const ulonglong2*>(w2 + (e2 + i) * 8);
        ulonglong2 v1 = *reinterpret_cast<const ulonglong2*>(w2 + (e2 + i) * 8 + 4);
        wp[i][0] = v0.x; wp[i][1] = v0.y;
        wp[i][2] = v1.x; wp[i][3] = v1.y;
    }
    const float4 bias = *reinterpret_cast<const float4*>(b2 + e2);

    const int row0 = blockIdx.x * RPB2;

    // stage this tile's q (RPB2*8 floats = 64 float4)
    if (tid < 64)
        reinterpret_cast<float4*>(s_q)[tid] =
            reinterpret_cast<const float4*>(g_q + (size_t)row0 * 8)[tid];
    __syncthreads();

#pragma unroll 4
    for (int r = 0; r < RPB2; r++) {
        // broadcast LDS.128 x2: q row as 4 packed pairs
        ulonglong2 qv0 = *reinterpret_cast<const ulonglong2*>(&s_q[r * 8]);
        ulonglong2 qv1 = *reinterpret_cast<const ulonglong2*>(&s_q[r * 8 + 4]);

        float o[4];
#pragma unroll
        for (int i = 0; i < 4; i++) {
            u64 acc;
            MUL2(acc, qv0.x, wp[i][0]);
            FMA2(acc, qv0.y, wp[i][1], acc);
            FMA2(acc, qv1.x, wp[i][2], acc);
            FMA2(acc, qv1.y, wp[i][3], acc);
            float2 t = unpack2(acc);
            o[i] = t.x + t.y;
        }
        float4 res = make_float4(o[0] + bias.x, o[1] + bias.y,
                                 o[2] + bias.z, o[3] + bias.w);
        *reinterpret_cast<float4*>(out + (size_t)(row0 + r) * E_DIM + e2) = res;
    }
}

extern "C" void kernel_launch(void* const* d_in, const int* in_sizes, int n_in,
                              void* d_out, int out_size) {
    const float* x  = (const float*)d_in[0];
    const float* w1 = (const float*)d_in[1];
    const float* b1 = (const float*)d_in[2];
    const float* w2 = (const float*)d_in[3];
    const float* b2 = (const float*)d_in[4];
    float* out = (float*)d_out;

    const int rows = in_sizes[0] / E_DIM;        // 32768

    ffq_phase1<<<rows / RPB1, 256>>>(x, w1, b1, rows);   // 512 blocks
    ffq_phase2<<<rows / RPB2, 256>>>(w2, b2, out, rows); // 1024 blocks
}